// round 15
// baseline (speedup 1.0000x reference)
#include <cuda_runtime.h>
#include <cstdint>

// Problem constants (fixed by the dataset)
#define C_DIM 22
#define T_DIM 4000
#define M_DIM 16
#define B_DIM 16

// Tiling: 512-t double-buffered tiles, 8 tiles per item, 2 CTAs per SM.
#define TT    512
#define TPI   8          // ceil(4000/512), tail zero-filled
#define BLOCK 256

typedef unsigned long long u64;

// packed dual-fp32 FMA: d = a*b + c (elementwise on {lo,hi})
__device__ __forceinline__ u64 fma2(u64 a, u64 b, u64 c) {
    u64 d;
    asm("fma.rn.f32x2 %0, %1, %2, %3;" : "=l"(d) : "l"(a), "l"(b), "l"(c));
    return d;
}
__device__ __forceinline__ u64 dup2(float v) {
    u64 d; asm("mov.b64 %0, {%1, %1};" : "=l"(d) : "f"(v)); return d;
}

// Stage tile k of this item: 22 rows x 512 floats (45KB), 11 cp.async per thread.
// Zero-fills the t>=4000 tail (tile 7) without DRAM traffic.
__device__ __forceinline__ void stage_tile(float* dst, const float* __restrict__ gx,
                                           int k, int tid)
{
    const int tg = k * TT + ((tid & 127) << 2);      // global t of this 16B chunk
    const unsigned ss = (tg < T_DIM) ? 16u : 0u;     // src-size 0 => zero-fill
    const float* src = ss ? (gx + tg) : gx;          // clamp OOB address
    const int c0   = tid >> 7;                       // 0 or 1
    const int soff = (tid & 127) << 2;
    #pragma unroll
    for (int c = c0; c < C_DIM; c += 2) {
        unsigned sa = (unsigned)__cvta_generic_to_shared(dst + c * TT + soff);
        asm volatile("cp.async.cg.shared.global [%0], [%1], 16, %2;"
                     :: "r"(sa), "l"(src + c * T_DIM), "r"(ss));
    }
}

// One CTA per item (n*16+b). out[item,m] = log(diag[m]/sum_m diag[m]),
// diag[m] = sum_t (sum_c W[b,m,c]*x[c,t])^2. The reference's 1/sqrt(T)
// scaling cancels in the ratio and is skipped.
// W lives in smem as pre-duplicated f32x2 pairs so no W registers are held
// across the mainloop -> fits 2 CTAs/SM (independent barrier domains: one
// CTA computes while the other waits on DRAM).
__global__ void __launch_bounds__(BLOCK, 2)
csp_kernel(const float* __restrict__ xfb, const float* __restrict__ WT,
           float* __restrict__ out)
{
    extern __shared__ float sm[];
    float* xb  = sm;                                  // 2 * 22*512 floats
    u64*   w2  = (u64*)(sm + 2 * C_DIM * TT);         // 22*16 dup'd pairs (16B-aligned)
    float* red = (float*)(w2 + C_DIM * M_DIM);        // 32 floats scratch

    const int tid  = threadIdx.x;
    const int lane = tid & 31;
    const int wid  = tid >> 5;
    const int g    = wid & 3;                         // m-group: m in [4g, 4g+4)
    const int h    = wid >> 2;                        // t-half within a tile

    const int item = blockIdx.x;
    const float* gx = xfb + (size_t)item * (C_DIM * T_DIM);

    // Kick off DRAM immediately.
    stage_tile(xb, gx, 0, tid);
    asm volatile("cp.async.commit_group;");

    // Fill w2[c*16+m] = dup{W[b,m,c]} while tile 0 is in flight.
    {
        const float* wb = WT + (size_t)(item & (B_DIM - 1)) * (M_DIM * C_DIM);
        #pragma unroll
        for (int idx = tid; idx < C_DIM * M_DIM; idx += BLOCK) {
            const int m = idx & 15, c = idx >> 4;
            w2[idx] = dup2(__ldg(wb + m * C_DIM + c));
        }
    }

    u64 acc[4] = {0ull, 0ull, 0ull, 0ull};            // sum z^2, packed over t-pairs
    const int tlb = (h << 8) + (lane << 1);           // this thread's base t in a tile
    const u64* wp = w2 + 4 * g;                       // this warp's 4 m's

    #pragma unroll 1
    for (int k = 0; k < TPI; k++) {
        // Prefetch tile k+1 into the other slot (last read two barriers ago),
        // then wait for tile k. At k=7 drain everything.
        if (k + 1 < TPI) {
            stage_tile(xb + ((k + 1) & 1) * (C_DIM * TT), gx, k + 1, tid);
            asm volatile("cp.async.commit_group;");
            asm volatile("cp.async.wait_group 1;");
        } else {
            asm volatile("cp.async.wait_group 0;");
        }
        __syncthreads();   // tile k (and w2 at k=0) visible to all warps

        const float* xs = xb + (k & 1) * (C_DIM * TT) + tlb;

        u64 z[4][4];       // [m][t-pair], 16 independent FMA chains
        #pragma unroll
        for (int j = 0; j < 4; j++)
            z[j][0] = z[j][1] = z[j][2] = z[j][3] = 0ull;

        #pragma unroll
        for (int c = 0; c < C_DIM; c++) {
            const ulonglong2 p0 = *(const ulonglong2*)(wp + c * 16);      // m 4g,4g+1
            const ulonglong2 p1 = *(const ulonglong2*)(wp + c * 16 + 2);  // m 4g+2,4g+3
            #pragma unroll
            for (int tp = 0; tp < 4; tp++) {
                const u64 xd = *(const u64*)(xs + c * TT + tp * 64); // {t, t+1}
                z[0][tp] = fma2(p0.x, xd, z[0][tp]);
                z[1][tp] = fma2(p0.y, xd, z[1][tp]);
                z[2][tp] = fma2(p1.x, xd, z[2][tp]);
                z[3][tp] = fma2(p1.y, xd, z[3][tp]);
            }
        }
        #pragma unroll
        for (int j = 0; j < 4; j++) {
            acc[j] = fma2(z[j][0], z[j][0], acc[j]);
            acc[j] = fma2(z[j][1], z[j][1], acc[j]);
            acc[j] = fma2(z[j][2], z[j][2], acc[j]);
            acc[j] = fma2(z[j][3], z[j][3], acc[j]);
        }
        __syncthreads();   // all reads of this slot done before it is re-staged
    }

    // ---- reduction: diag[m] over lanes, then over the two t-half warps ----
    float a0, a1, a2, a3;
    {
        float lo, hi;
        asm("mov.b64 {%0, %1}, %2;" : "=f"(lo), "=f"(hi) : "l"(acc[0])); a0 = lo + hi;
        asm("mov.b64 {%0, %1}, %2;" : "=f"(lo), "=f"(hi) : "l"(acc[1])); a1 = lo + hi;
        asm("mov.b64 {%0, %1}, %2;" : "=f"(lo), "=f"(hi) : "l"(acc[2])); a2 = lo + hi;
        asm("mov.b64 {%0, %1}, %2;" : "=f"(lo), "=f"(hi) : "l"(acc[3])); a3 = lo + hi;
    }
    #pragma unroll
    for (int off = 16; off; off >>= 1) {
        a0 += __shfl_xor_sync(0xffffffffu, a0, off);
        a1 += __shfl_xor_sync(0xffffffffu, a1, off);
        a2 += __shfl_xor_sync(0xffffffffu, a2, off);
        a3 += __shfl_xor_sync(0xffffffffu, a3, off);
    }
    if (lane == 0) {
        red[(h << 4) + g * 4 + 0] = a0;
        red[(h << 4) + g * 4 + 1] = a1;
        red[(h << 4) + g * 4 + 2] = a2;
        red[(h << 4) + g * 4 + 3] = a3;
    }
    __syncthreads();
    if (tid < M_DIM) red[tid] = red[tid] + red[M_DIM + tid];
    __syncthreads();
    if (tid < M_DIM) {
        float tot = 0.f;
        #pragma unroll
        for (int j = 0; j < M_DIM; j++) tot += red[j];
        out[item * M_DIM + tid] = logf(red[tid] / tot);
    }
}

extern "C" void kernel_launch(void* const* d_in, const int* in_sizes, int n_in,
                              void* d_out, int out_size) {
    const float* xfb = (const float*)d_in[0];
    const float* WT  = (const float*)d_in[1];
    int nx = in_sizes[0];
    // Defensive: ensure xfb is the big tensor
    if (n_in >= 2 && in_sizes[0] < in_sizes[1]) {
        xfb = (const float*)d_in[1];
        WT  = (const float*)d_in[0];
        nx  = in_sizes[1];
    }
    const int n_items = nx / (C_DIM * T_DIM);        // = 1024 (N*B)

    const size_t smem_bytes =
        (size_t)(2 * C_DIM * TT) * sizeof(float)     // x double buffer (90,112 B)
        + (size_t)(C_DIM * M_DIM) * sizeof(u64)      // dup'd W pairs   ( 2,816 B)
        + 32 * sizeof(float);                        // reduction scratch

    cudaFuncSetAttribute((const void*)csp_kernel,
                         cudaFuncAttributeMaxDynamicSharedMemorySize,
                         (int)smem_bytes);

    csp_kernel<<<n_items, BLOCK, smem_bytes>>>(xfb, WT, (float*)d_out);
}